// round 12
// baseline (speedup 1.0000x reference)
#include <cuda_runtime.h>
#include <math.h>

// Problem constants
#define BB 4
#define TT 512
#define DD 192
#define CHK 32
#define NC (TT/CHK)        // 16 chunks per batch
#define NBC (BB*NC)        // 64 chunk-blocks total
#define PAD 196            // smem row pitch (floats) for 192-wide tiles
#define VP  100            // smem pitch for 96-wide tiles
#define WXP 130            // Xt pitch (128 m + 2 pad)
#define SP  96             // S-panel pitch (floats)

// ---------------- scratch (module-static device memory; no allocations) ----------------
__device__ float g_Q[BB*TT*DD];
__device__ float g_K[BB*TT*DD];
__device__ float g_V[BB*TT*DD];
__device__ float g_G  [(size_t)NBC*DD*DD];   // per-chunk K^T V   (9.4 MB)
__device__ float g_Sst[(size_t)NBC*DD*DD];   // exclusive prefix state (+S0)
__device__ float g_z  [(size_t)NBC*DD];      // per-chunk sum of K rows
__device__ float g_zst[(size_t)NBC*DD];      // exclusive prefix (+Z0)
__device__ float g_A  [(size_t)2*NBC*CHK*CHK]; // k-split partial scores

__device__ __forceinline__ float elu1(float v) {
    return v > 0.f ? v + 1.f : expf(v);
}

// ---- packed fp32x2 helpers (FFMA2) ----
__device__ __forceinline__ unsigned long long pack2(float lo, float hi) {
    unsigned long long r;
    asm("mov.b64 %0, {%1, %2};" : "=l"(r) : "f"(lo), "f"(hi));
    return r;
}
__device__ __forceinline__ void ffma2(unsigned long long& d,
                                      unsigned long long a, unsigned long long b) {
    asm("fma.rn.f32x2 %0, %1, %2, %0;" : "+l"(d) : "l"(a), "l"(b));
}
__device__ __forceinline__ void unpack2(unsigned long long v, float& lo, float& hi) {
    asm("mov.b64 {%0, %1}, %2;" : "=f"(lo), "=f"(hi) : "l"(v));
}

// ---------------- Kernel 1: qkv = x @ W^T + b, elu+1 on Q,K (FFMA2, m-paired) ----------
__global__ __launch_bounds__(256) void qkv_kernel(const float* __restrict__ x,
                                                  const float* __restrict__ W,
                                                  const float* __restrict__ bias) {
    extern __shared__ float sm[];
    float* Xt = sm;              // [192][WXP]  k-major, m contiguous
    float* Ws = sm + DD*WXP;     // [64][PAD]   n-major, k contiguous
    const int tid = threadIdx.x;
    const int m0 = blockIdx.x * 128;
    const int n0 = blockIdx.y * 64;

    for (int idx = tid; idx < 128*48; idx += 256) {
        int r = idx / 48, c4 = (idx % 48) * 4;
        float4 xv = *reinterpret_cast<const float4*>(x + (size_t)(m0 + r)*DD + c4);
        Xt[(c4+0)*WXP + r] = xv.x;
        Xt[(c4+1)*WXP + r] = xv.y;
        Xt[(c4+2)*WXP + r] = xv.z;
        Xt[(c4+3)*WXP + r] = xv.w;
    }
    for (int idx = tid; idx < 64*48; idx += 256) {
        int r = idx / 48, c4 = (idx % 48) * 4;
        *reinterpret_cast<float4*>(Ws + r*PAD + c4) =
            *reinterpret_cast<const float4*>(W + (size_t)(n0 + r)*DD + c4);
    }
    __syncthreads();

    const int tm = tid & 15;   // m pair lane: m = 2*tm + 32*v
    const int ty = tid >> 4;   // n lane:      n = ty + 16*u
    unsigned long long acc2[4][4];
    #pragma unroll
    for (int v = 0; v < 4; v++)
        #pragma unroll
        for (int u = 0; u < 4; u++) acc2[v][u] = 0ull;

    for (int k = 0; k < DD; k++) {
        unsigned long long a[4];
        #pragma unroll
        for (int v = 0; v < 4; v++)
            a[v] = *reinterpret_cast<const unsigned long long*>(Xt + k*WXP + 2*tm + 32*v);
        #pragma unroll
        for (int u = 0; u < 4; u++) {
            float wv = Ws[(ty + 16*u)*PAD + k];
            unsigned long long wd = pack2(wv, wv);
            #pragma unroll
            for (int v = 0; v < 4; v++) ffma2(acc2[v][u], a[v], wd);
        }
    }

    #pragma unroll
    for (int u = 0; u < 4; u++) {
        int n = n0 + ty + 16*u;
        float bv = bias[n];
        #pragma unroll
        for (int v = 0; v < 4; v++) {
            float lo, hi; unpack2(acc2[v][u], lo, hi);
            int m = m0 + 2*tm + 32*v;
            float v0 = lo + bv, v1 = hi + bv;
            if (n < DD) {
                g_Q[(size_t)m*DD + n]     = elu1(v0);
                g_Q[(size_t)(m+1)*DD + n] = elu1(v1);
            } else if (n < 2*DD) {
                g_K[(size_t)m*DD + (n-DD)]     = elu1(v0);
                g_K[(size_t)(m+1)*DD + (n-DD)] = elu1(v1);
            } else {
                g_V[(size_t)m*DD + (n-2*DD)]     = v0;
                g_V[(size_t)(m+1)*DD + (n-2*DD)] = v1;
            }
        }
    }
}

// ---------------- Kernel 2: per-chunk G = K^T V (j-half) + z + A partial (k-half) ------
__global__ __launch_bounds__(256) void chunkscore_kernel() {
    extern __shared__ float sm[];
    float* Ks = sm;               // [32][PAD]  full i range of K
    float* Vs = Ks + CHK*PAD;     // [32][VP]   this block's j-half of V
    float* Qk = Vs + CHK*VP;      // [32][VP]   this block's k-half of Q
    const int tid = threadIdx.x;
    const int bc = blockIdx.x >> 1;
    const int jh = blockIdx.x & 1;
    const int j0 = jh * 96;
    const int b = bc / NC, c = bc % NC;
    const size_t tbase = ((size_t)b*TT + (size_t)c*CHK) * DD;

    for (int idx = tid; idx < CHK*48; idx += 256) {
        int r = idx / 48, c4 = (idx % 48) * 4;
        *reinterpret_cast<float4*>(Ks + r*PAD + c4) =
            *reinterpret_cast<const float4*>(g_K + tbase + (size_t)r*DD + c4);
    }
    for (int idx = tid; idx < CHK*24; idx += 256) {
        int r = idx / 24, c4 = (idx % 24) * 4;
        *reinterpret_cast<float4*>(Vs + r*VP + c4) =
            *reinterpret_cast<const float4*>(g_V + tbase + (size_t)r*DD + j0 + c4);
        *reinterpret_cast<float4*>(Qk + r*VP + c4) =
            *reinterpret_cast<const float4*>(g_Q + tbase + (size_t)r*DD + j0 + c4);
    }
    __syncthreads();

    if (jh == 0 && tid < DD) {
        float zs = 0.f;
        #pragma unroll
        for (int s = 0; s < CHK; s++) zs += Ks[s*PAD + tid];
        g_z[(size_t)bc*DD + tid] = zs;
    }

    const int tx = tid & 15, ty = tid >> 4;

    // A partial for k-half jh: A[t][s] = sum_{k in half} Q[t][k] * K[s][k]
    {
        float a2[2][2] = {{0.f,0.f},{0.f,0.f}};
        for (int k = 0; k < 96; k++) {
            float q[2], kk[2];
            #pragma unroll
            for (int r = 0; r < 2; r++) q[r]  = Qk[(ty + 16*r)*VP + k];
            #pragma unroll
            for (int e = 0; e < 2; e++) kk[e] = Ks[(tx + 16*e)*PAD + j0 + k];
            #pragma unroll
            for (int r = 0; r < 2; r++)
                #pragma unroll
                for (int e = 0; e < 2; e++) a2[r][e] += q[r]*kk[e];
        }
        float* Ap = g_A + ((size_t)jh*NBC + bc)*(CHK*CHK);
        #pragma unroll
        for (int r = 0; r < 2; r++)
            #pragma unroll
            for (int e = 0; e < 2; e++)
                Ap[(ty + 16*r)*CHK + tx + 16*e] = a2[r][e];
    }

    // G = K^T V for this j-half (FFMA2 over j pairs)
    unsigned long long acc2[12][3];
    #pragma unroll
    for (int a = 0; a < 12; a++)
        #pragma unroll
        for (int e = 0; e < 3; e++) acc2[a][e] = 0ull;

    #pragma unroll 4
    for (int s = 0; s < CHK; s++) {
        unsigned long long kd[12], vj[3];
        #pragma unroll
        for (int a = 0; a < 12; a++) {
            float kv = Ks[s*PAD + ty + 16*a];
            kd[a] = pack2(kv, kv);
        }
        #pragma unroll
        for (int e = 0; e < 3; e++)
            vj[e] = *reinterpret_cast<const unsigned long long*>(Vs + s*VP + 2*tx + 32*e);
        #pragma unroll
        for (int a = 0; a < 12; a++)
            #pragma unroll
            for (int e = 0; e < 3; e++) ffma2(acc2[a][e], kd[a], vj[e]);
    }

    float* Gp = g_G + (size_t)bc*(DD*DD);
    #pragma unroll
    for (int a = 0; a < 12; a++) {
        int i = ty + 16*a;
        #pragma unroll
        for (int e = 0; e < 3; e++) {
            float lo, hi; unpack2(acc2[a][e], lo, hi);
            *reinterpret_cast<float2*>(Gp + (size_t)i*DD + j0 + 2*tx + 32*e) =
                make_float2(lo, hi);
        }
    }
}

// ---------------- Kernel 3: fused exclusive prefix (S and z), float4 lanes -------------
__global__ __launch_bounds__(256) void prefix_kernel(const float* __restrict__ S0,
                                                     const float* __restrict__ Z0,
                                                     float* __restrict__ outS,
                                                     float* __restrict__ outZ) {
    const int tid = threadIdx.x;
    if (blockIdx.x < 144) {
        int e4 = blockIdx.x * 256 + tid;             // < B*D*D/4 = 36864
        int b = e4 / (DD*DD/4), r4 = e4 - b*(DD*DD/4);
        const float* Gp = g_G + (size_t)b*NC*DD*DD + (size_t)r4*4;
        float*       Sp = g_Sst + (size_t)b*NC*DD*DD + (size_t)r4*4;
        float4 v[NC];
        #pragma unroll
        for (int c = 0; c < NC; c++)
            v[c] = *reinterpret_cast<const float4*>(Gp + (size_t)c*DD*DD);
        float4 run = *reinterpret_cast<const float4*>(S0 + (size_t)e4*4);
        #pragma unroll
        for (int c = 0; c < NC; c++) {
            float4 nv = make_float4(run.x + v[c].x, run.y + v[c].y,
                                    run.z + v[c].z, run.w + v[c].w);
            v[c] = run; run = nv;
        }
        #pragma unroll
        for (int c = 0; c < NC; c++)
            *reinterpret_cast<float4*>(Sp + (size_t)c*DD*DD) = v[c];
        *reinterpret_cast<float4*>(outS + (size_t)e4*4) = run;  // S[:, -1]
    } else {
        int e4 = tid;                                 // < B*D/4 = 192
        if (e4 >= BB*DD/4) return;
        int b = e4 / (DD/4), i4 = e4 - b*(DD/4);
        const float* zp = g_z  + (size_t)b*NC*DD + (size_t)i4*4;
        float*      zsp = g_zst + (size_t)b*NC*DD + (size_t)i4*4;
        float4 v[NC];
        #pragma unroll
        for (int c = 0; c < NC; c++)
            v[c] = *reinterpret_cast<const float4*>(zp + (size_t)c*DD);
        float4 run = *reinterpret_cast<const float4*>(Z0 + (size_t)e4*4);
        #pragma unroll
        for (int c = 0; c < NC; c++) {
            float4 nv = make_float4(run.x + v[c].x, run.y + v[c].y,
                                    run.z + v[c].z, run.w + v[c].w);
            v[c] = run; run = nv;
        }
        #pragma unroll
        for (int c = 0; c < NC; c++)
            *reinterpret_cast<float4*>(zsp + (size_t)c*DD) = v[c];
        *reinterpret_cast<float4*>(outZ + (size_t)e4*4) = run;
    }
}

// ---------------- Kernel 4: per-chunk output, 512 threads, i-split halves ---------------
// grid = 64 chunks x 2 j-halves.  Block covers 32t x 96j.
// ih = tid>>8 splits the reduction: ih=0 does i in [0,96) and s in [0,16),
// ih=1 does i in [96,192) and s in [16,32). Partials combined via smem.
// Full S panel (192x96) preloaded to smem once -> only 2 __syncthreads.
__global__ __launch_bounds__(512) void out_kernel(float* __restrict__ out) {
    extern __shared__ float sm[];
    float* Ss   = sm;                   // [192][SP]  S panel (j-half)   73.7 KB
    float* Qs   = Ss + DD*SP;           // [32][PAD]                     25 KB
    float* Vs   = Qs + CHK*PAD;         // [32][VP]   (j-half)           12.8 KB
    float* As   = Vs + CHK*VP;          // [32][33]   masked scores      4.2 KB
    float* dens = As + CHK*33;          // [32]
    float* red  = dens + 32;            // [256][12]  partial reduction  12 KB

    const int tid = threadIdx.x;
    const int bc = blockIdx.x >> 1;
    const int jh = blockIdx.x & 1;
    const int j0 = jh * 96;
    const int b = bc / NC, c = bc % NC;
    const size_t tbase = ((size_t)b*TT + (size_t)c*CHK) * DD;

    // ---- load phase ----
    const float* Sp = g_Sst + (size_t)bc*(DD*DD);
    #pragma unroll
    for (int q = 0; q < 9; q++) {
        int fi = tid + 512*q;                 // < 4608 float4s
        int r = fi / 24, c4 = (fi % 24) * 4;
        *reinterpret_cast<float4*>(Ss + r*SP + c4) =
            *reinterpret_cast<const float4*>(Sp + (size_t)r*DD + j0 + c4);
    }
    #pragma unroll
    for (int q = 0; q < 3; q++) {
        int fi = tid + 512*q;                 // < 1536 float4s
        int r = fi / 48, c4 = (fi % 48) * 4;
        *reinterpret_cast<float4*>(Qs + r*PAD + c4) =
            *reinterpret_cast<const float4*>(g_Q + tbase + (size_t)r*DD + c4);
    }
    for (int fi = tid; fi < CHK*24; fi += 512) {
        int r = fi / 24, c4 = (fi % 24) * 4;
        *reinterpret_cast<float4*>(Vs + r*VP + c4) =
            *reinterpret_cast<const float4*>(g_V + tbase + (size_t)r*DD + j0 + c4);
    }
    {
        const float* A0 = g_A + (size_t)bc*(CHK*CHK);
        const float* A1 = g_A + ((size_t)NBC + bc)*(CHK*CHK);
        #pragma unroll
        for (int q = 0; q < 2; q++) {
            int idx = tid + 512*q;            // < 1024
            int t_ = idx >> 5, s_ = idx & 31;
            float a = A0[idx] + A1[idx];
            As[t_*33 + s_] = (s_ <= t_) ? a : 0.f;
        }
    }
    __syncthreads();

    // denominators (threads 0..31, overlapped with main loop of other warps)
    if (tid < CHK) {
        const float* zp = g_zst + (size_t)bc*DD;
        float ds = 0.f;
        for (int k = 0; k < DD; k++) ds += Qs[tid*PAD + k] * zp[k];
        #pragma unroll
        for (int s = 0; s < CHK; s++) ds += As[tid*33 + s];
        dens[tid] = ds + 1e-5f;
    }

    const int ih  = tid >> 8;     // reduction half
    const int tl  = tid & 255;
    const int tjp = tl & 7;       // j = 4*tjp + 32*u, u < 3
    const int tt  = tl >> 3;      // t row 0..31

    unsigned long long acc2[3][2];
    #pragma unroll
    for (int u = 0; u < 3; u++) { acc2[u][0] = 0ull; acc2[u][1] = 0ull; }

    // intra-chunk: masked A @ V  (s-half)
    #pragma unroll 4
    for (int s = ih*16; s < ih*16 + 16; s++) {
        float a = As[tt*33 + s];
        unsigned long long ad = pack2(a, a);
        #pragma unroll
        for (int u = 0; u < 3; u++) {
            ulonglong2 vv = *reinterpret_cast<const ulonglong2*>(Vs + s*VP + 4*tjp + 32*u);
            ffma2(acc2[u][0], ad, vv.x);
            ffma2(acc2[u][1], ad, vv.y);
        }
    }

    // inter-chunk: Q @ S_start  (i-half), S panel resident in smem
    #pragma unroll 4
    for (int i = ih*96; i < ih*96 + 96; i++) {
        float q = Qs[tt*PAD + i];
        unsigned long long qd = pack2(q, q);
        #pragma unroll
        for (int u = 0; u < 3; u++) {
            ulonglong2 sv = *reinterpret_cast<const ulonglong2*>(Ss + i*SP + 4*tjp + 32*u);
            ffma2(acc2[u][0], qd, sv.x);
            ffma2(acc2[u][1], qd, sv.y);
        }
    }

    // ih=1 publishes partials
    if (ih == 1) {
        #pragma unroll
        for (int u = 0; u < 3; u++) {
            float x0, x1, x2, x3;
            unpack2(acc2[u][0], x0, x1);
            unpack2(acc2[u][1], x2, x3);
            *reinterpret_cast<float4*>(red + tl*12 + u*4) = make_float4(x0, x1, x2, x3);
        }
    }
    __syncthreads();

    // ih=0 combines + stores
    if (ih == 0) {
        float dv = dens[tt];
        #pragma unroll
        for (int u = 0; u < 3; u++) {
            float x0, x1, x2, x3;
            unpack2(acc2[u][0], x0, x1);
            unpack2(acc2[u][1], x2, x3);
            float4 pr = *reinterpret_cast<const float4*>(red + tl*12 + u*4);
            float4 r4 = make_float4((x0 + pr.x)/dv, (x1 + pr.y)/dv,
                                    (x2 + pr.z)/dv, (x3 + pr.w)/dv);
            *reinterpret_cast<float4*>(out + tbase + (size_t)tt*DD + j0 + 4*tjp + 32*u) = r4;
        }
    }
}

// ---------------- launch ----------------------------------------------------------------
extern "C" void kernel_launch(void* const* d_in, const int* in_sizes, int n_in,
                              void* d_out, int out_size) {
    const float* x  = (const float*)d_in[0];
    const float* W  = (const float*)d_in[1];
    const float* bi = (const float*)d_in[2];
    const float* S0 = (const float*)d_in[3];
    const float* Z0 = (const float*)d_in[4];
    float* out = (float*)d_out;

    const int SM1 = (DD*WXP + 64*PAD)*4;                          // 150016 B
    const int SM2 = (CHK*PAD + 2*CHK*VP)*4;                       // 50688 B
    const int SM4 = (DD*SP + CHK*PAD + CHK*VP + CHK*33 + 32 + 256*12)*4; // 128256 B
    cudaFuncSetAttribute(qkv_kernel, cudaFuncAttributeMaxDynamicSharedMemorySize, SM1);
    cudaFuncSetAttribute(chunkscore_kernel, cudaFuncAttributeMaxDynamicSharedMemorySize, SM2);
    cudaFuncSetAttribute(out_kernel, cudaFuncAttributeMaxDynamicSharedMemorySize, SM4);

    qkv_kernel<<<dim3(16, 9), 256, SM1>>>(x, W, bi);
    chunkscore_kernel<<<2*NBC, 256, SM2>>>();
    prefix_kernel<<<145, 256>>>(S0, Z0,
                                out + (size_t)BB*TT*DD,
                                out + (size_t)BB*TT*DD + (size_t)BB*DD*DD);
    out_kernel<<<2*NBC, 512, SM4>>>(out);
}

// round 13
// speedup vs baseline: 1.1390x; 1.1390x over previous
#include <cuda_runtime.h>
#include <math.h>

// Problem constants
#define BB 4
#define TT 512
#define DD 192
#define CHK 32
#define NC (TT/CHK)        // 16 chunks per batch
#define NBC (BB*NC)        // 64 chunk-blocks total
#define PAD 196            // smem row pitch (floats) for 192-wide tiles
#define VP  100            // smem pitch for 96-wide tiles
#define WXP 130            // Xt pitch (128 m + 2 pad)
#define SP  96             // S/V panel pitch (floats)
#define QTP 36             // Qt/At pitch (32 t + 4 pad)
#define ORS 224            // unified rows: 192 S-rows + 32 V-rows

// ---------------- scratch (module-static device memory; no allocations) ----------------
__device__ float g_Q[BB*TT*DD];
__device__ float g_K[BB*TT*DD];
__device__ float g_V[BB*TT*DD];
__device__ float g_G  [(size_t)NBC*DD*DD];   // per-chunk K^T V   (9.4 MB)
__device__ float g_Sst[(size_t)NBC*DD*DD];   // exclusive prefix state (+S0)
__device__ float g_z  [(size_t)NBC*DD];      // per-chunk sum of K rows
__device__ float g_zst[(size_t)NBC*DD];      // exclusive prefix (+Z0)
__device__ float g_A  [(size_t)2*NBC*CHK*CHK]; // k-split partial scores

__device__ __forceinline__ float elu1(float v) {
    return v > 0.f ? v + 1.f : expf(v);
}

// ---- packed fp32x2 helpers (FFMA2) ----
__device__ __forceinline__ unsigned long long pack2(float lo, float hi) {
    unsigned long long r;
    asm("mov.b64 %0, {%1, %2};" : "=l"(r) : "f"(lo), "f"(hi));
    return r;
}
__device__ __forceinline__ void ffma2(unsigned long long& d,
                                      unsigned long long a, unsigned long long b) {
    asm("fma.rn.f32x2 %0, %1, %2, %0;" : "+l"(d) : "l"(a), "l"(b));
}
__device__ __forceinline__ void unpack2(unsigned long long v, float& lo, float& hi) {
    asm("mov.b64 {%0, %1}, %2;" : "=f"(lo), "=f"(hi) : "l"(v));
}

// ---------------- Kernel 1: qkv = x @ W^T + b, elu+1 on Q,K (FFMA2, m-paired) ----------
__global__ __launch_bounds__(256) void qkv_kernel(const float* __restrict__ x,
                                                  const float* __restrict__ W,
                                                  const float* __restrict__ bias) {
    extern __shared__ float sm[];
    float* Xt = sm;              // [192][WXP]  k-major, m contiguous
    float* Ws = sm + DD*WXP;     // [64][PAD]   n-major, k contiguous
    const int tid = threadIdx.x;
    const int m0 = blockIdx.x * 128;
    const int n0 = blockIdx.y * 64;

    for (int idx = tid; idx < 128*48; idx += 256) {
        int r = idx / 48, c4 = (idx % 48) * 4;
        float4 xv = *reinterpret_cast<const float4*>(x + (size_t)(m0 + r)*DD + c4);
        Xt[(c4+0)*WXP + r] = xv.x;
        Xt[(c4+1)*WXP + r] = xv.y;
        Xt[(c4+2)*WXP + r] = xv.z;
        Xt[(c4+3)*WXP + r] = xv.w;
    }
    for (int idx = tid; idx < 64*48; idx += 256) {
        int r = idx / 48, c4 = (idx % 48) * 4;
        *reinterpret_cast<float4*>(Ws + r*PAD + c4) =
            *reinterpret_cast<const float4*>(W + (size_t)(n0 + r)*DD + c4);
    }
    __syncthreads();

    const int tm = tid & 15;   // m pair lane: m = 2*tm + 32*v
    const int ty = tid >> 4;   // n lane:      n = ty + 16*u
    unsigned long long acc2[4][4];
    #pragma unroll
    for (int v = 0; v < 4; v++)
        #pragma unroll
        for (int u = 0; u < 4; u++) acc2[v][u] = 0ull;

    for (int k = 0; k < DD; k++) {
        unsigned long long a[4];
        #pragma unroll
        for (int v = 0; v < 4; v++)
            a[v] = *reinterpret_cast<const unsigned long long*>(Xt + k*WXP + 2*tm + 32*v);
        #pragma unroll
        for (int u = 0; u < 4; u++) {
            float wv = Ws[(ty + 16*u)*PAD + k];
            unsigned long long wd = pack2(wv, wv);
            #pragma unroll
            for (int v = 0; v < 4; v++) ffma2(acc2[v][u], a[v], wd);
        }
    }

    #pragma unroll
    for (int u = 0; u < 4; u++) {
        int n = n0 + ty + 16*u;
        float bv = bias[n];
        #pragma unroll
        for (int v = 0; v < 4; v++) {
            float lo, hi; unpack2(acc2[v][u], lo, hi);
            int m = m0 + 2*tm + 32*v;
            float v0 = lo + bv, v1 = hi + bv;
            if (n < DD) {
                g_Q[(size_t)m*DD + n]     = elu1(v0);
                g_Q[(size_t)(m+1)*DD + n] = elu1(v1);
            } else if (n < 2*DD) {
                g_K[(size_t)m*DD + (n-DD)]     = elu1(v0);
                g_K[(size_t)(m+1)*DD + (n-DD)] = elu1(v1);
            } else {
                g_V[(size_t)m*DD + (n-2*DD)]     = v0;
                g_V[(size_t)(m+1)*DD + (n-2*DD)] = v1;
            }
        }
    }
}

// ---------------- Kernel 2: per-chunk G = K^T V (j-half) + z + A partial (k-half) ------
__global__ __launch_bounds__(256) void chunkscore_kernel() {
    extern __shared__ float sm[];
    float* Ks = sm;               // [32][PAD]  full i range of K
    float* Vs = Ks + CHK*PAD;     // [32][VP]   this block's j-half of V
    float* Qk = Vs + CHK*VP;      // [32][VP]   this block's k-half of Q
    const int tid = threadIdx.x;
    const int bc = blockIdx.x >> 1;
    const int jh = blockIdx.x & 1;
    const int j0 = jh * 96;
    const int b = bc / NC, c = bc % NC;
    const size_t tbase = ((size_t)b*TT + (size_t)c*CHK) * DD;

    for (int idx = tid; idx < CHK*48; idx += 256) {
        int r = idx / 48, c4 = (idx % 48) * 4;
        *reinterpret_cast<float4*>(Ks + r*PAD + c4) =
            *reinterpret_cast<const float4*>(g_K + tbase + (size_t)r*DD + c4);
    }
    for (int idx = tid; idx < CHK*24; idx += 256) {
        int r = idx / 24, c4 = (idx % 24) * 4;
        *reinterpret_cast<float4*>(Vs + r*VP + c4) =
            *reinterpret_cast<const float4*>(g_V + tbase + (size_t)r*DD + j0 + c4);
        *reinterpret_cast<float4*>(Qk + r*VP + c4) =
            *reinterpret_cast<const float4*>(g_Q + tbase + (size_t)r*DD + j0 + c4);
    }
    __syncthreads();

    if (jh == 0 && tid < DD) {
        float zs = 0.f;
        #pragma unroll
        for (int s = 0; s < CHK; s++) zs += Ks[s*PAD + tid];
        g_z[(size_t)bc*DD + tid] = zs;
    }

    const int tx = tid & 15, ty = tid >> 4;

    // A partial for k-half jh: A[t][s] = sum_{k in half} Q[t][k] * K[s][k]
    {
        float a2[2][2] = {{0.f,0.f},{0.f,0.f}};
        for (int k = 0; k < 96; k++) {
            float q[2], kk[2];
            #pragma unroll
            for (int r = 0; r < 2; r++) q[r]  = Qk[(ty + 16*r)*VP + k];
            #pragma unroll
            for (int e = 0; e < 2; e++) kk[e] = Ks[(tx + 16*e)*PAD + j0 + k];
            #pragma unroll
            for (int r = 0; r < 2; r++)
                #pragma unroll
                for (int e = 0; e < 2; e++) a2[r][e] += q[r]*kk[e];
        }
        float* Ap = g_A + ((size_t)jh*NBC + bc)*(CHK*CHK);
        #pragma unroll
        for (int r = 0; r < 2; r++)
            #pragma unroll
            for (int e = 0; e < 2; e++)
                Ap[(ty + 16*r)*CHK + tx + 16*e] = a2[r][e];
    }

    // G = K^T V for this j-half (FFMA2 over j pairs)
    unsigned long long acc2[12][3];
    #pragma unroll
    for (int a = 0; a < 12; a++)
        #pragma unroll
        for (int e = 0; e < 3; e++) acc2[a][e] = 0ull;

    #pragma unroll 4
    for (int s = 0; s < CHK; s++) {
        unsigned long long kd[12], vj[3];
        #pragma unroll
        for (int a = 0; a < 12; a++) {
            float kv = Ks[s*PAD + ty + 16*a];
            kd[a] = pack2(kv, kv);
        }
        #pragma unroll
        for (int e = 0; e < 3; e++)
            vj[e] = *reinterpret_cast<const unsigned long long*>(Vs + s*VP + 2*tx + 32*e);
        #pragma unroll
        for (int a = 0; a < 12; a++)
            #pragma unroll
            for (int e = 0; e < 3; e++) ffma2(acc2[a][e], kd[a], vj[e]);
    }

    float* Gp = g_G + (size_t)bc*(DD*DD);
    #pragma unroll
    for (int a = 0; a < 12; a++) {
        int i = ty + 16*a;
        #pragma unroll
        for (int e = 0; e < 3; e++) {
            float lo, hi; unpack2(acc2[a][e], lo, hi);
            *reinterpret_cast<float2*>(Gp + (size_t)i*DD + j0 + 2*tx + 32*e) =
                make_float2(lo, hi);
        }
    }
}

// ---------------- Kernel 3: fused exclusive prefix (S and z), float4 lanes -------------
__global__ __launch_bounds__(256) void prefix_kernel(const float* __restrict__ S0,
                                                     const float* __restrict__ Z0,
                                                     float* __restrict__ outS,
                                                     float* __restrict__ outZ) {
    const int tid = threadIdx.x;
    if (blockIdx.x < 144) {
        int e4 = blockIdx.x * 256 + tid;             // < B*D*D/4 = 36864
        int b = e4 / (DD*DD/4), r4 = e4 - b*(DD*DD/4);
        const float* Gp = g_G + (size_t)b*NC*DD*DD + (size_t)r4*4;
        float*       Sp = g_Sst + (size_t)b*NC*DD*DD + (size_t)r4*4;
        float4 v[NC];
        #pragma unroll
        for (int c = 0; c < NC; c++)
            v[c] = *reinterpret_cast<const float4*>(Gp + (size_t)c*DD*DD);
        float4 run = *reinterpret_cast<const float4*>(S0 + (size_t)e4*4);
        #pragma unroll
        for (int c = 0; c < NC; c++) {
            float4 nv = make_float4(run.x + v[c].x, run.y + v[c].y,
                                    run.z + v[c].z, run.w + v[c].w);
            v[c] = run; run = nv;
        }
        #pragma unroll
        for (int c = 0; c < NC; c++)
            *reinterpret_cast<float4*>(Sp + (size_t)c*DD*DD) = v[c];
        *reinterpret_cast<float4*>(outS + (size_t)e4*4) = run;  // S[:, -1]
    } else {
        int e4 = tid;                                 // < B*D/4 = 192
        if (e4 >= BB*DD/4) return;
        int b = e4 / (DD/4), i4 = e4 - b*(DD/4);
        const float* zp = g_z  + (size_t)b*NC*DD + (size_t)i4*4;
        float*      zsp = g_zst + (size_t)b*NC*DD + (size_t)i4*4;
        float4 v[NC];
        #pragma unroll
        for (int c = 0; c < NC; c++)
            v[c] = *reinterpret_cast<const float4*>(zp + (size_t)c*DD);
        float4 run = *reinterpret_cast<const float4*>(Z0 + (size_t)e4*4);
        #pragma unroll
        for (int c = 0; c < NC; c++) {
            float4 nv = make_float4(run.x + v[c].x, run.y + v[c].y,
                                    run.z + v[c].z, run.w + v[c].w);
            v[c] = run; run = nv;
        }
        #pragma unroll
        for (int c = 0; c < NC; c++)
            *reinterpret_cast<float4*>(zsp + (size_t)c*DD) = v[c];
        *reinterpret_cast<float4*>(outZ + (size_t)e4*4) = run;
    }
}

// ---------------- Kernel 4: per-chunk output — unified 224-row GEMM --------------------
// grid = 64 chunks x 2 j-halves, 512 threads.
// SV rows:  0..191 = S_start panel (j-half), 192..223 = V rows.
// QtA rows: 0..191 = Q^T (Qt[i][t]), 192..223 = masked A^T (At[s][t]).
// out[t][j] = (sum_r QtA[r][t] * SV[r][j]) / dens[t]
// 8 slices of 28 rows; per thread 4t x 12j register tile; 24 FFMA2 per 4 LDS.128.
__global__ __launch_bounds__(512) void out_kernel(float* __restrict__ out) {
    extern __shared__ float sm[];
    float* SV   = sm;                    // [224][SP]   86016 B
    float* QtA  = SV + ORS*SP;           // [224][QTP]  32256 B
    float* zs   = QtA + ORS*QTP;         // [192]
    float* dens = zs + DD;               // [32]
    float* red  = sm;                    // overlay after compute (7*64*52 floats)

    const int tid = threadIdx.x;
    const int bc = blockIdx.x >> 1;
    const int jh = blockIdx.x & 1;
    const int j0 = jh * 96;
    const int b = bc / NC, c = bc % NC;
    const size_t tbase = ((size_t)b*TT + (size_t)c*CHK) * DD;

    // ---- load phase ----
    const float* Sp = g_Sst + (size_t)bc*(DD*DD);
    #pragma unroll
    for (int q = 0; q < 9; q++) {
        int fi = tid + 512*q;                 // < 4608 float4s
        int r = fi / 24, c4 = (fi % 24) * 4;
        *reinterpret_cast<float4*>(SV + r*SP + c4) =
            *reinterpret_cast<const float4*>(Sp + (size_t)r*DD + j0 + c4);
    }
    for (int fi = tid; fi < CHK*24; fi += 512) {    // V rows
        int r = fi / 24, c4 = (fi % 24) * 4;
        *reinterpret_cast<float4*>(SV + (192 + r)*SP + c4) =
            *reinterpret_cast<const float4*>(g_V + tbase + (size_t)r*DD + j0 + c4);
    }
    #pragma unroll
    for (int q = 0; q < 3; q++) {                   // Qt transpose
        int fi = tid + 512*q;                 // < 1536
        int t = fi & 31, i4 = fi >> 5;        // i4 < 48
        float4 qv = *reinterpret_cast<const float4*>(g_Q + tbase + (size_t)t*DD + i4*4);
        QtA[(i4*4+0)*QTP + t] = qv.x;
        QtA[(i4*4+1)*QTP + t] = qv.y;
        QtA[(i4*4+2)*QTP + t] = qv.z;
        QtA[(i4*4+3)*QTP + t] = qv.w;
    }
    {                                               // At = masked (A0+A1)^T
        const float* A0 = g_A + (size_t)bc*(CHK*CHK);
        const float* A1 = g_A + ((size_t)NBC + bc)*(CHK*CHK);
        #pragma unroll
        for (int q = 0; q < 2; q++) {
            int idx = tid + 512*q;            // < 1024
            int s = idx >> 5, t = idx & 31;
            float a = A0[t*CHK + s] + A1[t*CHK + s];
            QtA[(192 + s)*QTP + t] = (s <= t) ? a : 0.f;
        }
    }
    if (tid < 48) {                                 // z_start to smem
        *reinterpret_cast<float4*>(zs + 4*tid) =
            *reinterpret_cast<const float4*>(g_zst + (size_t)bc*DD + 4*tid);
    }
    __syncthreads();

    // denominators by warp 14 (slice 7's first warp): dens[t] = sum_r QtA[r][t]*w[r]
    if ((tid >> 5) == 14) {
        int t = tid & 31;
        float d0 = 0.f, d1 = 0.f;
        for (int r = 0; r < 192; r += 2) {
            d0 += QtA[r*QTP + t] * zs[r];
            d1 += QtA[(r+1)*QTP + t] * zs[r+1];
        }
        #pragma unroll
        for (int s = 0; s < 32; s += 2) {
            d0 += QtA[(192+s)*QTP + t];
            d1 += QtA[(193+s)*QTP + t];
        }
        dens[t] = d0 + d1 + 1e-5f;
    }

    const int slice = tid >> 6;      // 0..7, rows [28*slice, 28*slice+28)
    const int l     = tid & 63;
    const int tg    = l >> 3;        // t rows 4tg..4tg+3
    const int tjp   = l & 7;         // j = 4*tjp + 32*u
    const int r0    = slice * 28;

    unsigned long long acc[4][3][2];
    #pragma unroll
    for (int p = 0; p < 4; p++)
        #pragma unroll
        for (int u = 0; u < 3; u++) { acc[p][u][0] = 0ull; acc[p][u][1] = 0ull; }

    const float* qrow = QtA + r0*QTP + 4*tg;
    const float* srow = SV + r0*SP + 4*tjp;

    // software-pipelined main loop
    float4 qv = *reinterpret_cast<const float4*>(qrow);
    ulonglong2 s0 = *reinterpret_cast<const ulonglong2*>(srow);
    ulonglong2 s1 = *reinterpret_cast<const ulonglong2*>(srow + 32);
    ulonglong2 s2 = *reinterpret_cast<const ulonglong2*>(srow + 64);
    #pragma unroll 4
    for (int rr = 0; rr < 28; rr++) {
        float4 qn; ulonglong2 n0, n1, n2;
        if (rr < 27) {
            qn = *reinterpret_cast<const float4*>(qrow + (rr+1)*QTP);
            n0 = *reinterpret_cast<const ulonglong2*>(srow + (rr+1)*SP);
            n1 = *reinterpret_cast<const ulonglong2*>(srow + (rr+1)*SP + 32);
            n2 = *reinterpret_cast<const ulonglong2*>(srow + (rr+1)*SP + 64);
        }
        unsigned long long qd[4];
        qd[0] = pack2(qv.x, qv.x); qd[1] = pack2(qv.y, qv.y);
        qd[2] = pack2(qv.z, qv.z); qd[3] = pack2(qv.w, qv.w);
        #pragma unroll
        for (int p = 0; p < 4; p++) {
            ffma2(acc[p][0][0], qd[p], s0.x); ffma2(acc[p][0][1], qd[p], s0.y);
            ffma2(acc[p][1][0], qd[p], s1.x); ffma2(acc[p][1][1], qd[p], s1.y);
            ffma2(acc[p][2][0], qd[p], s2.x); ffma2(acc[p][2][1], qd[p], s2.y);
        }
        qv = qn; s0 = n0; s1 = n1; s2 = n2;
    }
    __syncthreads();   // all slices done reading SV/QtA; SV becomes red

    if (slice != 0) {
        float* rp = red + ((size_t)(slice-1)*64 + l) * 52;
        #pragma unroll
        for (int p = 0; p < 4; p++)
            #pragma unroll
            for (int u = 0; u < 3; u++) {
                float a0, a1, a2, a3;
                unpack2(acc[p][u][0], a0, a1);
                unpack2(acc[p][u][1], a2, a3);
                *reinterpret_cast<float4*>(rp + (p*3+u)*4) = make_float4(a0, a1, a2, a3);
            }
    }
    __syncthreads();

    if (slice == 0) {
        float r48[12][4];
        #pragma unroll
        for (int p = 0; p < 4; p++)
            #pragma unroll
            for (int u = 0; u < 3; u++) {
                unpack2(acc[p][u][0], r48[p*3+u][0], r48[p*3+u][1]);
                unpack2(acc[p][u][1], r48[p*3+u][2], r48[p*3+u][3]);
            }
        #pragma unroll
        for (int sl = 1; sl < 8; sl++) {
            const float* rp = red + ((size_t)(sl-1)*64 + l) * 52;
            #pragma unroll
            for (int k = 0; k < 12; k++) {
                float4 pv = *reinterpret_cast<const float4*>(rp + k*4);
                r48[k][0] += pv.x; r48[k][1] += pv.y;
                r48[k][2] += pv.z; r48[k][3] += pv.w;
            }
        }
        #pragma unroll
        for (int p = 0; p < 4; p++) {
            int t = 4*tg + p;
            float inv = 1.0f / dens[t];
            #pragma unroll
            for (int u = 0; u < 3; u++) {
                int k = p*3 + u;
                *reinterpret_cast<float4*>(out + tbase + (size_t)t*DD + j0 + 4*tjp + 32*u) =
                    make_float4(r48[k][0]*inv, r48[k][1]*inv,
                                r48[k][2]*inv, r48[k][3]*inv);
            }
        }
    }
}

// ---------------- launch ----------------------------------------------------------------
extern "C" void kernel_launch(void* const* d_in, const int* in_sizes, int n_in,
                              void* d_out, int out_size) {
    const float* x  = (const float*)d_in[0];
    const float* W  = (const float*)d_in[1];
    const float* bi = (const float*)d_in[2];
    const float* S0 = (const float*)d_in[3];
    const float* Z0 = (const float*)d_in[4];
    float* out = (float*)d_out;

    const int SM1 = (DD*WXP + 64*PAD)*4;                    // 150016 B
    const int SM2 = (CHK*PAD + 2*CHK*VP)*4;                 // 50688 B
    const int SM4 = (ORS*SP + ORS*QTP + DD + 32)*4;         // 119168 B
    cudaFuncSetAttribute(qkv_kernel, cudaFuncAttributeMaxDynamicSharedMemorySize, SM1);
    cudaFuncSetAttribute(chunkscore_kernel, cudaFuncAttributeMaxDynamicSharedMemorySize, SM2);
    cudaFuncSetAttribute(out_kernel, cudaFuncAttributeMaxDynamicSharedMemorySize, SM4);

    qkv_kernel<<<dim3(16, 9), 256, SM1>>>(x, W, bi);
    chunkscore_kernel<<<2*NBC, 256, SM2>>>();
    prefix_kernel<<<145, 256>>>(S0, Z0,
                                out + (size_t)BB*TT*DD,
                                out + (size_t)BB*TT*DD + (size_t)BB*DD*DD);
    out_kernel<<<2*NBC, 512, SM4>>>(out);
}